// round 1
// baseline (speedup 1.0000x reference)
#include <cuda_runtime.h>

#define BB   8
#define DIMM 1024
#define TLEN 4096
#define CBN  4096
#define CDN  8

#define OUT_ELEMS (BB*DIMM*TLEN)          /* 33554432 */
#define IDX_OFF   OUT_ELEMS
#define LOSS_OFF  (OUT_ELEMS + BB*TLEN)   /* 33587200 */
#define NTILES    ((BB*TLEN)/32)          /* 1024 */

typedef unsigned long long u64;

// ---------------- scratch (device globals; no allocs allowed) ----------------
__device__ __align__(16) float g_Wt[DIMM*CDN];     // W_in^T  [d][o]          (8 floats / d)
__device__ __align__(16) float g_WoutP[DIMM*CDN];  // paired: [p][k][2] = (W[2p][k], W[2p+1][k])
__device__ __align__(16) float g_cnp[CBN*CDN];     // paired normalized codebook [jp][k][2]
__device__ __align__(16) float g_csq[CBN];         // ||c_n||^2 per code (natural pairs)
__device__ float g_partial[NTILES];                // per-tile loss partial sums

// ---------------- packed f32x2 helpers (FFMA2 only reachable via PTX) --------
__device__ __forceinline__ u64 fma2(u64 a, u64 b, u64 c) {
    u64 d; asm("fma.rn.f32x2 %0,%1,%2,%3;" : "=l"(d) : "l"(a), "l"(b), "l"(c)); return d;
}
__device__ __forceinline__ u64 mul2(u64 a, u64 b) {
    u64 d; asm("mul.rn.f32x2 %0,%1,%2;" : "=l"(d) : "l"(a), "l"(b)); return d;
}
__device__ __forceinline__ u64 add2(u64 a, u64 b) {
    u64 d; asm("add.rn.f32x2 %0,%1,%2;" : "=l"(d) : "l"(a), "l"(b)); return d;
}
__device__ __forceinline__ u64 pack2(float lo, float hi) {
    u64 d; asm("mov.b64 %0,{%1,%2};" : "=l"(d) : "f"(lo), "f"(hi)); return d;
}
__device__ __forceinline__ void unpack2(u64 v, float &lo, float &hi) {
    asm("mov.b64 {%0,%1},%2;" : "=f"(lo), "=f"(hi) : "l"(v));
}

// ---------------- prep: weight-norm + normalized codebook (paired layouts) ---
__global__ void prep_kernel(const float* __restrict__ v_in,  const float* __restrict__ g_in,
                            const float* __restrict__ cb,
                            const float* __restrict__ v_out, const float* __restrict__ g_out)
{
    int bid = blockIdx.x, tid = threadIdx.x;

    if (bid < 32) {
        // normalized codebook rows: c_n = c / max(||c||, 1e-12); paired-interleaved store
        int j = bid * 128 + tid;                       // 0..4095
        const float4* r = (const float4*)(cb + j * 8);
        float4 a = __ldg(r), b = __ldg(r + 1);
        float v[8] = {a.x, a.y, a.z, a.w, b.x, b.y, b.z, b.w};
        float s = 0.f;
#pragma unroll
        for (int k = 0; k < 8; k++) s = fmaf(v[k], v[k], s);
        float den = fmaxf(__fsqrt_rn(s), 1e-12f);
        float c[8];
#pragma unroll
        for (int k = 0; k < 8; k++) c[k] = __fdiv_rn(v[k], den);
        float cs = 0.f;
#pragma unroll
        for (int k = 0; k < 8; k++) cs = fmaf(c[k], c[k], cs);
        g_csq[j] = cs;
        int jp = j >> 1, h = j & 1;
#pragma unroll
        for (int k = 0; k < 8; k++) g_cnp[jp * 16 + k * 2 + h] = c[k];
    } else if (bid < 40) {
        // W_out rows: weight_norm over CD=8; paired-interleaved store
        int o = (bid - 32) * 128 + tid;                // 0..1023
        const float4* r = (const float4*)(v_out + o * 8);
        float4 a = __ldg(r), b = __ldg(r + 1);
        float v[8] = {a.x, a.y, a.z, a.w, b.x, b.y, b.z, b.w};
        float s = 0.f;
#pragma unroll
        for (int k = 0; k < 8; k++) s = fmaf(v[k], v[k], s);
        float n = __fsqrt_rn(s);
        float g = __ldg(g_out + o);
        int p = o >> 1, h = o & 1;
#pragma unroll
        for (int k = 0; k < 8; k++) g_WoutP[p * 16 + k * 2 + h] = __fdiv_rn(g * v[k], n);
    } else {
        // W_in: 8 rows, norms over 1024; transpose store g_Wt[d][o]
        __shared__ float nrm[8];
        int o = tid >> 4, l = tid & 15;                // 8 groups x 16 lanes
        float s = 0.f;
        for (int d = l; d < DIMM; d += 16) {
            float v = v_in[o * DIMM + d];
            s = fmaf(v, v, s);
        }
#pragma unroll
        for (int off = 8; off >= 1; off >>= 1) s += __shfl_down_sync(0xffffffffu, s, off, 16);
        if (l == 0) nrm[o] = __fsqrt_rn(s);
        __syncthreads();
        for (int e = tid; e < DIMM * CDN; e += 128) {
            int d = e >> 3, oo = e & 7;
            g_Wt[e] = __fdiv_rn(__ldg(g_in + oo) * v_in[oo * DIMM + d], nrm[oo]);
        }
    }
}

// ---------------- fused main: in_proj -> argmin -> gather/loss -> out_proj ---
__global__ void __launch_bounds__(32)
vq_main_kernel(const float* __restrict__ z, const float* __restrict__ b_in,
               const float* __restrict__ cb, const float* __restrict__ b_out,
               float* __restrict__ out, int write_idx)
{
    const int lane = threadIdx.x;
    const int tf = blockIdx.x * 32 + lane;     // flattened (b,t)
    const int b  = tf >> 12;
    const int t  = tf & (TLEN - 1);

    // ---- in_proj: z_e[o] = W_in[o,:] . z[b,:,t] + b_in[o] -------------------
    const float* zb = z + (size_t)b * DIMM * TLEN + t;
    u64 acc[4] = {0, 0, 0, 0};
    const ulonglong2* wt = (const ulonglong2*)g_Wt;
#pragma unroll 8
    for (int d = 0; d < DIMM; d++) {
        float zv = __ldcg(zb + (size_t)d * TLEN);       // stream z, bypass L1
        u64 zz = pack2(zv, zv);
        ulonglong2 wA = __ldg(wt + d * 2);
        ulonglong2 wB = __ldg(wt + d * 2 + 1);
        acc[0] = fma2(wA.x, zz, acc[0]);
        acc[1] = fma2(wA.y, zz, acc[1]);
        acc[2] = fma2(wB.x, zz, acc[2]);
        acc[3] = fma2(wB.y, zz, acc[3]);
    }
    const u64* binp = (const u64*)b_in;
    float ze[8];
#pragma unroll
    for (int o2 = 0; o2 < 4; o2++) {
        u64 v = add2(acc[o2], __ldg(binp + o2));
        unpack2(v, ze[2 * o2], ze[2 * o2 + 1]);
    }

    // ---- normalize query ----------------------------------------------------
    float s = 0.f;
#pragma unroll
    for (int k = 0; k < 8; k++) s = fmaf(ze[k], ze[k], s);
    float den = fmaxf(__fsqrt_rn(s), 1e-12f);
    float q[8];
#pragma unroll
    for (int k = 0; k < 8; k++) q[k] = __fdiv_rn(ze[k], den);
    float esq = 0.f;
#pragma unroll
    for (int k = 0; k < 8; k++) esq = fmaf(q[k], q[k], esq);
    u64 qq[8];
#pragma unroll
    for (int k = 0; k < 8; k++) qq[k] = pack2(q[k], q[k]);
    const u64 esq2 = pack2(esq, esq);
    const u64 two2 = pack2(2.0f, 2.0f);
    const u64 SGN  = 0x8000000080000000ull;

    // ---- argmin over 4096 codes, 2 codes / iter via f32x2 -------------------
    // dist = (e_sq - 2*dot) + c_sq  (replicates reference rounding order)
    float dmin = 3.402823466e38f;
    int   imin = 0;
    const ulonglong2* cp0 = (const ulonglong2*)g_cnp;
    const u64* csqp = (const u64*)g_csq;
#pragma unroll 4
    for (int jp = 0; jp < CBN / 2; jp++) {
        const ulonglong2* cp = cp0 + jp * 4;
        ulonglong2 c0 = __ldg(cp), c1 = __ldg(cp + 1), c2 = __ldg(cp + 2), c3 = __ldg(cp + 3);
        u64 dot = 0;
        dot = fma2(c0.x, qq[0], dot); dot = fma2(c0.y, qq[1], dot);
        dot = fma2(c1.x, qq[2], dot); dot = fma2(c1.y, qq[3], dot);
        dot = fma2(c2.x, qq[4], dot); dot = fma2(c2.y, qq[5], dot);
        dot = fma2(c3.x, qq[6], dot); dot = fma2(c3.y, qq[7], dot);
        u64 m  = mul2(dot, two2) ^ SGN;                 // -(2*dot), exact
        u64 t1 = add2(esq2, m);                         // e_sq - 2*dot
        u64 d2 = add2(t1, __ldg(csqp + jp));            // + c_sq
        float dx, dy; unpack2(d2, dx, dy);
        if (dx < dmin) { dmin = dx; imin = 2 * jp; }
        if (dy < dmin) { dmin = dy; imin = 2 * jp + 1; }
    }

    // ---- gather raw code, STE, commitment loss ------------------------------
    const float4* cr = (const float4*)(cb + imin * 8);
    float4 cA = __ldg(cr), cB = __ldg(cr + 1);
    float zq[8] = {cA.x, cA.y, cA.z, cA.w, cB.x, cB.y, cB.z, cB.w};
    float loss = 0.f, zs[8];
#pragma unroll
    for (int k = 0; k < 8; k++) {
        float df = ze[k] - zq[k];
        loss = fmaf(df, df, loss);
        zs[k] = ze[k] + (zq[k] - ze[k]);                // straight-through value
    }
#pragma unroll
    for (int off = 16; off >= 1; off >>= 1) loss += __shfl_down_sync(0xffffffffu, loss, off);
    if (lane == 0) g_partial[blockIdx.x] = loss;
    if (write_idx) out[IDX_OFF + tf] = (float)imin;

    // ---- out_proj: out[b,o,t] = W_out[o,:] . zs + b_out[o] ------------------
    u64 zz2[8];
#pragma unroll
    for (int k = 0; k < 8; k++) zz2[k] = pack2(zs[k], zs[k]);
    float* ob = out + (size_t)b * DIMM * TLEN + t;
    const ulonglong2* wp0 = (const ulonglong2*)g_WoutP;
    const u64* boutp = (const u64*)b_out;
#pragma unroll 4
    for (int p = 0; p < DIMM / 2; p++) {
        const ulonglong2* wp = wp0 + p * 4;
        ulonglong2 w0 = __ldg(wp), w1 = __ldg(wp + 1), w2 = __ldg(wp + 2), w3 = __ldg(wp + 3);
        u64 a2 = 0;
        a2 = fma2(w0.x, zz2[0], a2); a2 = fma2(w0.y, zz2[1], a2);
        a2 = fma2(w1.x, zz2[2], a2); a2 = fma2(w1.y, zz2[3], a2);
        a2 = fma2(w2.x, zz2[4], a2); a2 = fma2(w2.y, zz2[5], a2);
        a2 = fma2(w3.x, zz2[6], a2); a2 = fma2(w3.y, zz2[7], a2);
        a2 = add2(a2, __ldg(boutp + p));
        float vx, vy; unpack2(a2, vx, vy);
        __stcg(ob + (size_t)(2 * p) * TLEN, vx);
        __stcg(ob + (size_t)(2 * p + 1) * TLEN, vy);
    }
}

// ---------------- deterministic loss finalization ----------------------------
__global__ void loss_final_kernel(float* __restrict__ out, int write_loss)
{
    if (!write_loss) return;
    int b = threadIdx.x;
    if (b >= BB) return;
    float s = 0.f;
    for (int i = 0; i < NTILES / BB; i++)               // fixed order -> deterministic
        s += g_partial[b * (NTILES / BB) + i];
    // 1.25/32768 is exactly representable; equals mean*0.25 + mean bit-for-bit
    out[LOSS_OFF + b] = s * (1.25f / 32768.0f);
}

// ---------------- launch -----------------------------------------------------
extern "C" void kernel_launch(void* const* d_in, const int* in_sizes, int n_in,
                              void* d_out, int out_size)
{
    const float* z     = (const float*)d_in[0];
    const float* v_in  = (const float*)d_in[1];
    const float* g_in  = (const float*)d_in[2];
    const float* b_in  = (const float*)d_in[3];
    const float* cb    = (const float*)d_in[4];
    const float* v_out = (const float*)d_in[5];
    const float* g_out = (const float*)d_in[6];
    const float* b_out = (const float*)d_in[7];
    float* out = (float*)d_out;

    int write_idx  = (out_size >= IDX_OFF + BB * TLEN) ? 1 : 0;
    int write_loss = (out_size >= LOSS_OFF + BB) ? 1 : 0;

    prep_kernel<<<41, 128>>>(v_in, g_in, cb, v_out, g_out);
    vq_main_kernel<<<NTILES, 32>>>(z, b_in, cb, b_out, out, write_idx);
    loss_final_kernel<<<1, 32>>>(out, write_loss);
}

// round 2
// speedup vs baseline: 3.2341x; 3.2341x over previous
#include <cuda_runtime.h>

#define BB   8
#define DIMM 1024
#define TLEN 4096
#define CBN  4096
#define CDN  8
#define TILE 32

#define OUT_ELEMS (BB*DIMM*TLEN)          /* 33554432 */
#define IDX_OFF   OUT_ELEMS
#define LOSS_OFF  (OUT_ELEMS + BB*TLEN)   /* 33587200 */
#define NTILES    ((BB*TLEN)/TILE)        /* 1024 */

typedef unsigned long long u64;

// ---------------- scratch (device globals; no allocs allowed) ----------------
__device__ __align__(16) float g_Wt[DIMM*CDN];     // W_in^T  [d][o]
__device__ __align__(16) float g_WoutP[DIMM*CDN];  // paired: [p][k][2] = (W[2p][k], W[2p+1][k])
__device__ __align__(16) float g_cnp[CBN*CDN];     // paired normalized codebook [jp][k][2]
__device__ __align__(16) float g_csq[CBN];         // ||c_n||^2 per code (natural pairs)
__device__ float g_partial[NTILES];                // per-tile loss partial sums

// ---------------- packed f32x2 helpers ---------------------------------------
__device__ __forceinline__ u64 fma2(u64 a, u64 b, u64 c) {
    u64 d; asm("fma.rn.f32x2 %0,%1,%2,%3;" : "=l"(d) : "l"(a), "l"(b), "l"(c)); return d;
}
__device__ __forceinline__ u64 mul2(u64 a, u64 b) {
    u64 d; asm("mul.rn.f32x2 %0,%1,%2;" : "=l"(d) : "l"(a), "l"(b)); return d;
}
__device__ __forceinline__ u64 add2(u64 a, u64 b) {
    u64 d; asm("add.rn.f32x2 %0,%1,%2;" : "=l"(d) : "l"(a), "l"(b)); return d;
}
__device__ __forceinline__ u64 pack2(float lo, float hi) {
    u64 d; asm("mov.b64 %0,{%1,%2};" : "=l"(d) : "f"(lo), "f"(hi)); return d;
}
__device__ __forceinline__ void unpack2(u64 v, float &lo, float &hi) {
    asm("mov.b64 {%0,%1},%2;" : "=f"(lo), "=f"(hi) : "l"(v));
}

// ---------------- prep: weight-norm + normalized codebook (paired layouts) ---
__global__ void prep_kernel(const float* __restrict__ v_in,  const float* __restrict__ g_in,
                            const float* __restrict__ cb,
                            const float* __restrict__ v_out, const float* __restrict__ g_out)
{
    int bid = blockIdx.x, tid = threadIdx.x;

    if (bid < 32) {
        int j = bid * 128 + tid;
        const float4* r = (const float4*)(cb + j * 8);
        float4 a = __ldg(r), b = __ldg(r + 1);
        float v[8] = {a.x, a.y, a.z, a.w, b.x, b.y, b.z, b.w};
        float s = 0.f;
#pragma unroll
        for (int k = 0; k < 8; k++) s = fmaf(v[k], v[k], s);
        float den = fmaxf(__fsqrt_rn(s), 1e-12f);
        float c[8];
#pragma unroll
        for (int k = 0; k < 8; k++) c[k] = __fdiv_rn(v[k], den);
        float cs = 0.f;
#pragma unroll
        for (int k = 0; k < 8; k++) cs = fmaf(c[k], c[k], cs);
        g_csq[j] = cs;
        int jp = j >> 1, h = j & 1;
#pragma unroll
        for (int k = 0; k < 8; k++) g_cnp[jp * 16 + k * 2 + h] = c[k];
    } else if (bid < 40) {
        int o = (bid - 32) * 128 + tid;
        const float4* r = (const float4*)(v_out + o * 8);
        float4 a = __ldg(r), b = __ldg(r + 1);
        float v[8] = {a.x, a.y, a.z, a.w, b.x, b.y, b.z, b.w};
        float s = 0.f;
#pragma unroll
        for (int k = 0; k < 8; k++) s = fmaf(v[k], v[k], s);
        float n = __fsqrt_rn(s);
        float g = __ldg(g_out + o);
        int p = o >> 1, h = o & 1;
#pragma unroll
        for (int k = 0; k < 8; k++) g_WoutP[p * 16 + k * 2 + h] = __fdiv_rn(g * v[k], n);
    } else {
        __shared__ float nrm[8];
        int o = tid >> 4, l = tid & 15;
        float s = 0.f;
        for (int d = l; d < DIMM; d += 16) {
            float v = v_in[o * DIMM + d];
            s = fmaf(v, v, s);
        }
#pragma unroll
        for (int off = 8; off >= 1; off >>= 1) s += __shfl_down_sync(0xffffffffu, s, off, 16);
        if (l == 0) nrm[o] = __fsqrt_rn(s);
        __syncthreads();
        for (int e = tid; e < DIMM * CDN; e += 128) {
            int d = e >> 3, oo = e & 7;
            g_Wt[e] = __fdiv_rn(__ldg(g_in + oo) * v_in[oo * DIMM + d], nrm[oo]);
        }
    }
}

// ---------------- fused main (8 warps cooperate on 32 timesteps) -------------
__global__ void __launch_bounds__(256, 2)
vq_main_kernel(const float* __restrict__ z, const float* __restrict__ b_in,
               const float* __restrict__ cb, const float* __restrict__ b_out,
               float* __restrict__ out, int write_idx)
{
    __shared__ float s_part[8][TILE][9];   // [warp][t][o], pitch 9 vs bank conflicts
    __shared__ float s_ze[TILE][9];
    __shared__ float s_zs[TILE][9];
    __shared__ float s_dmin[8][TILE];
    __shared__ int   s_imin[8][TILE];

    const int tid  = threadIdx.x;
    const int w    = tid >> 5;
    const int lane = tid & 31;
    const int tf0  = blockIdx.x * TILE;    // 32 consecutive t, all same b
    const int b    = tf0 >> 12;
    const int t0   = tf0 & (TLEN - 1);

    // ---- phase 1: in_proj partials. warp w covers d in [128w, 128w+128) ----
    {
        const float* zb = z + (size_t)b * DIMM * TLEN + t0 + lane;
        u64 acc[4] = {0, 0, 0, 0};
        const ulonglong2* wt = (const ulonglong2*)g_Wt;
        const int d0 = w * 128;
#pragma unroll 8
        for (int i = 0; i < 128; i++) {
            int d = d0 + i;
            float zv = __ldcg(zb + (size_t)d * TLEN);
            u64 zz = pack2(zv, zv);
            ulonglong2 wA = __ldg(wt + d * 2);
            ulonglong2 wB = __ldg(wt + d * 2 + 1);
            acc[0] = fma2(wA.x, zz, acc[0]);
            acc[1] = fma2(wA.y, zz, acc[1]);
            acc[2] = fma2(wB.x, zz, acc[2]);
            acc[3] = fma2(wB.y, zz, acc[3]);
        }
#pragma unroll
        for (int o2 = 0; o2 < 4; o2++) {
            float lo, hi; unpack2(acc[o2], lo, hi);
            s_part[w][lane][2 * o2]     = lo;
            s_part[w][lane][2 * o2 + 1] = hi;
        }
    }
    __syncthreads();

    // ---- reduce partials (fixed ascending-w order, bias last — deterministic)
    {
        int t = tid >> 3, o = tid & 7;
        float s = 0.f;
#pragma unroll
        for (int ww = 0; ww < 8; ww++) s += s_part[ww][t][o];
        s += __ldg(b_in + o);
        s_ze[t][o] = s;
    }
    __syncthreads();

    // ---- phase 2: argmin. lane = t; warp w scans codes [512w, 512w+512) ----
    float ze[8];
#pragma unroll
    for (int k = 0; k < 8; k++) ze[k] = s_ze[lane][k];

    {
        float s = 0.f;
#pragma unroll
        for (int k = 0; k < 8; k++) s = fmaf(ze[k], ze[k], s);
        float den = fmaxf(__fsqrt_rn(s), 1e-12f);
        float q[8];
#pragma unroll
        for (int k = 0; k < 8; k++) q[k] = __fdiv_rn(ze[k], den);
        float esq = 0.f;
#pragma unroll
        for (int k = 0; k < 8; k++) esq = fmaf(q[k], q[k], esq);
        u64 qq[8];
#pragma unroll
        for (int k = 0; k < 8; k++) qq[k] = pack2(q[k], q[k]);
        const u64 esq2 = pack2(esq, esq);
        const u64 two2 = pack2(2.0f, 2.0f);
        const u64 SGN  = 0x8000000080000000ull;

        float dmin = 3.402823466e38f;
        int   imin = 0;
        const ulonglong2* cp0 = (const ulonglong2*)g_cnp;
        const u64* csqp = (const u64*)g_csq;
        const int jp0 = w * 256;
#pragma unroll 4
        for (int i = 0; i < 256; i++) {
            int jp = jp0 + i;
            const ulonglong2* cp = cp0 + jp * 4;
            ulonglong2 c0 = __ldg(cp), c1 = __ldg(cp + 1), c2 = __ldg(cp + 2), c3 = __ldg(cp + 3);
            u64 dot = 0;
            dot = fma2(c0.x, qq[0], dot); dot = fma2(c0.y, qq[1], dot);
            dot = fma2(c1.x, qq[2], dot); dot = fma2(c1.y, qq[3], dot);
            dot = fma2(c2.x, qq[4], dot); dot = fma2(c2.y, qq[5], dot);
            dot = fma2(c3.x, qq[6], dot); dot = fma2(c3.y, qq[7], dot);
            u64 m  = mul2(dot, two2) ^ SGN;             // -(2*dot), exact
            u64 t1 = add2(esq2, m);                     // e_sq - 2*dot
            u64 d2 = add2(t1, __ldg(csqp + jp));        // + c_sq
            float dx, dy; unpack2(d2, dx, dy);
            if (dx < dmin) { dmin = dx; imin = 2 * jp; }
            if (dy < dmin) { dmin = dy; imin = 2 * jp + 1; }
        }
        s_dmin[w][lane] = dmin;
        s_imin[w][lane] = imin;
    }
    __syncthreads();

    // ---- phase 3a (warp 0): global min (ascending w, strict < = first-min),
    //      gather raw code, loss, straight-through values, index output ------
    if (w == 0) {
        float dm = s_dmin[0][lane];
        int   im = s_imin[0][lane];
#pragma unroll
        for (int ww = 1; ww < 8; ww++) {
            float d = s_dmin[ww][lane];
            if (d < dm) { dm = d; im = s_imin[ww][lane]; }
        }
        const float4* cr = (const float4*)(cb + (size_t)im * 8);
        float4 cA = __ldg(cr), cB = __ldg(cr + 1);
        float zq[8] = {cA.x, cA.y, cA.z, cA.w, cB.x, cB.y, cB.z, cB.w};
        float loss = 0.f;
#pragma unroll
        for (int k = 0; k < 8; k++) {
            float df = ze[k] - zq[k];
            loss = fmaf(df, df, loss);
            s_zs[lane][k] = ze[k] + (zq[k] - ze[k]);    // straight-through value
        }
#pragma unroll
        for (int off = 16; off >= 1; off >>= 1) loss += __shfl_down_sync(0xffffffffu, loss, off);
        if (lane == 0) g_partial[blockIdx.x] = loss;
        if (write_idx) out[IDX_OFF + tf0 + lane] = (float)im;
    }
    __syncthreads();

    // ---- phase 3b: out_proj. lane = t; warp w covers o in [128w, 128w+128) --
    {
        u64 zz2[8];
#pragma unroll
        for (int k = 0; k < 8; k++) {
            float v = s_zs[lane][k];
            zz2[k] = pack2(v, v);
        }
        float* ob = out + (size_t)b * DIMM * TLEN + t0 + lane;
        const ulonglong2* wp0 = (const ulonglong2*)g_WoutP;
        const u64* boutp = (const u64*)b_out;
        const int p0 = w * 64;
#pragma unroll 4
        for (int i = 0; i < 64; i++) {
            int p = p0 + i;
            const ulonglong2* wp = wp0 + p * 4;
            ulonglong2 w0 = __ldg(wp), w1 = __ldg(wp + 1), w2 = __ldg(wp + 2), w3 = __ldg(wp + 3);
            u64 a2 = 0;
            a2 = fma2(w0.x, zz2[0], a2); a2 = fma2(w0.y, zz2[1], a2);
            a2 = fma2(w1.x, zz2[2], a2); a2 = fma2(w1.y, zz2[3], a2);
            a2 = fma2(w2.x, zz2[4], a2); a2 = fma2(w2.y, zz2[5], a2);
            a2 = fma2(w3.x, zz2[6], a2); a2 = fma2(w3.y, zz2[7], a2);
            a2 = add2(a2, __ldg(boutp + p));
            float vx, vy; unpack2(a2, vx, vy);
            __stcg(ob + (size_t)(2 * p) * TLEN, vx);
            __stcg(ob + (size_t)(2 * p + 1) * TLEN, vy);
        }
    }
}

// ---------------- deterministic loss finalization ----------------------------
__global__ void loss_final_kernel(float* __restrict__ out, int write_loss)
{
    if (!write_loss) return;
    int b = threadIdx.x;
    if (b >= BB) return;
    float s = 0.f;
    for (int i = 0; i < NTILES / BB; i++)               // fixed order -> deterministic
        s += g_partial[b * (NTILES / BB) + i];
    out[LOSS_OFF + b] = s * (1.25f / 32768.0f);
}

// ---------------- launch -----------------------------------------------------
extern "C" void kernel_launch(void* const* d_in, const int* in_sizes, int n_in,
                              void* d_out, int out_size)
{
    const float* z     = (const float*)d_in[0];
    const float* v_in  = (const float*)d_in[1];
    const float* g_in  = (const float*)d_in[2];
    const float* b_in  = (const float*)d_in[3];
    const float* cb    = (const float*)d_in[4];
    const float* v_out = (const float*)d_in[5];
    const float* g_out = (const float*)d_in[6];
    const float* b_out = (const float*)d_in[7];
    float* out = (float*)d_out;

    int write_idx  = (out_size >= IDX_OFF + BB * TLEN) ? 1 : 0;
    int write_loss = (out_size >= LOSS_OFF + BB) ? 1 : 0;

    prep_kernel<<<41, 128>>>(v_in, g_in, cb, v_out, g_out);
    vq_main_kernel<<<NTILES, 256>>>(z, b_in, cb, b_out, out, write_idx);
    loss_final_kernel<<<1, 32>>>(out, write_loss);
}

// round 3
// speedup vs baseline: 3.4824x; 1.0768x over previous
#include <cuda_runtime.h>

#define BB   8
#define DIMM 1024
#define TLEN 4096
#define CBN  4096
#define CDN  8
#define TILE 128

#define OUT_ELEMS (BB*DIMM*TLEN)          /* 33554432 */
#define IDX_OFF   OUT_ELEMS
#define LOSS_OFF  (OUT_ELEMS + BB*TLEN)   /* 33587200 */
#define NTILES    ((BB*TLEN)/TILE)        /* 256 */

typedef unsigned long long u64;

// ---------------- scratch (device globals; no allocs allowed) ----------------
__device__ __align__(16) float g_Wtd[DIMM*CDN*2];   // dup: [d][o][2] = (W[o][d], W[o][d])
__device__ __align__(16) float g_WoutD[DIMM*CDN*2]; // dup: [o][k][2]
__device__ __align__(16) float g_boutD[DIMM*2];     // dup bias out
__device__ __align__(16) float g_cnd[CBN*CDN*2];    // dup normalized codebook [j][k][2]
__device__ __align__(16) float g_csqD[CBN*2];       // dup ||c_n||^2
__device__ float g_partial[NTILES];

// ---------------- packed f32x2 helpers ---------------------------------------
__device__ __forceinline__ u64 fma2(u64 a, u64 b, u64 c) {
    u64 d; asm("fma.rn.f32x2 %0,%1,%2,%3;" : "=l"(d) : "l"(a), "l"(b), "l"(c)); return d;
}
__device__ __forceinline__ u64 add2(u64 a, u64 b) {
    u64 d; asm("add.rn.f32x2 %0,%1,%2;" : "=l"(d) : "l"(a), "l"(b)); return d;
}
__device__ __forceinline__ u64 pack2(float lo, float hi) {
    u64 d; asm("mov.b64 %0,{%1,%2};" : "=l"(d) : "f"(lo), "f"(hi)); return d;
}
__device__ __forceinline__ void unpack2(u64 v, float &lo, float &hi) {
    asm("mov.b64 {%0,%1},%2;" : "=f"(lo), "=f"(hi) : "l"(v));
}

// ---------------- prep: weight-norm + normalized codebook (dup layouts) ------
__global__ void prep_kernel(const float* __restrict__ v_in,  const float* __restrict__ g_in,
                            const float* __restrict__ cb,
                            const float* __restrict__ v_out, const float* __restrict__ g_out,
                            const float* __restrict__ b_out)
{
    int bid = blockIdx.x, tid = threadIdx.x;

    if (bid < 32) {
        int j = bid * 128 + tid;
        const float4* r = (const float4*)(cb + j * 8);
        float4 a = __ldg(r), b = __ldg(r + 1);
        float v[8] = {a.x, a.y, a.z, a.w, b.x, b.y, b.z, b.w};
        float s = 0.f;
#pragma unroll
        for (int k = 0; k < 8; k++) s = fmaf(v[k], v[k], s);
        float den = fmaxf(__fsqrt_rn(s), 1e-12f);
        float c[8];
#pragma unroll
        for (int k = 0; k < 8; k++) c[k] = __fdiv_rn(v[k], den);
        float cs = 0.f;
#pragma unroll
        for (int k = 0; k < 8; k++) cs = fmaf(c[k], c[k], cs);
        g_csqD[2 * j] = cs; g_csqD[2 * j + 1] = cs;
#pragma unroll
        for (int k = 0; k < 8; k++) {
            g_cnd[j * 16 + 2 * k]     = c[k];
            g_cnd[j * 16 + 2 * k + 1] = c[k];
        }
    } else if (bid < 40) {
        int o = (bid - 32) * 128 + tid;
        const float4* r = (const float4*)(v_out + o * 8);
        float4 a = __ldg(r), b = __ldg(r + 1);
        float v[8] = {a.x, a.y, a.z, a.w, b.x, b.y, b.z, b.w};
        float s = 0.f;
#pragma unroll
        for (int k = 0; k < 8; k++) s = fmaf(v[k], v[k], s);
        float n = __fsqrt_rn(s);
        float g = __ldg(g_out + o);
#pragma unroll
        for (int k = 0; k < 8; k++) {
            float wv = __fdiv_rn(g * v[k], n);
            g_WoutD[o * 16 + 2 * k]     = wv;
            g_WoutD[o * 16 + 2 * k + 1] = wv;
        }
        float bo = __ldg(b_out + o);
        g_boutD[2 * o] = bo; g_boutD[2 * o + 1] = bo;
    } else {
        __shared__ float nrm[8];
        int o = tid >> 4, l = tid & 15;
        float s = 0.f;
        for (int d = l; d < DIMM; d += 16) {
            float v = v_in[o * DIMM + d];
            s = fmaf(v, v, s);
        }
#pragma unroll
        for (int off = 8; off >= 1; off >>= 1) s += __shfl_down_sync(0xffffffffu, s, off, 16);
        if (l == 0) nrm[o] = __fsqrt_rn(s);
        __syncthreads();
        for (int e = tid; e < DIMM * CDN; e += 128) {
            int d = e >> 3, oo = e & 7;
            float wv = __fdiv_rn(__ldg(g_in + oo) * v_in[oo * DIMM + d], nrm[oo]);
            g_Wtd[d * 16 + 2 * oo]     = wv;
            g_Wtd[d * 16 + 2 * oo + 1] = wv;
        }
    }
}

// ---------------- fused main: TILE=128 t/block, 4 t per lane -----------------
// smem layout (bytes):
//   [0,36864)       s_part: float4 [8 warps][32 lanes][9 (8 o + pad)]
//   reuse of [0,36864) after reduce:
//     [0,4608)      s_q    : [128 t][9] = q[0..7], esq
//     [4608,9216)   s_zs   : [128 t][9]
//     [9216,13312)  s_dmin : [8 w][128 t]
//     [13312,17408) s_imin : [8 w][128 t]
//   [36864,41472)   s_ze   : [128 t][9]   (persistent)
//   [41472,41488)   s_lw   : [4]
__global__ void __launch_bounds__(256, 2)
vq_main_kernel(const float* __restrict__ z, const float* __restrict__ b_in,
               const float* __restrict__ cb, float* __restrict__ out, int write_idx)
{
    __shared__ __align__(16) unsigned char s_raw[41504];
    float* s_ze   = (float*)(s_raw + 36864);
    float* s_lw   = (float*)(s_raw + 41472);
    float* s_q    = (float*)(s_raw);
    float* s_zs   = (float*)(s_raw + 4608);
    float* s_dmin = (float*)(s_raw + 9216);
    int*   s_imin = (int*)  (s_raw + 13312);

    const int tid  = threadIdx.x;
    const int w    = tid >> 5;
    const int lane = tid & 31;
    const int tf0  = blockIdx.x * TILE;    // 128 consecutive t, all same b
    const int b    = tf0 >> 12;
    const int t0   = tf0 & (TLEN - 1);

    // ---- phase 1: in_proj partials. warp w covers d in [128w,128w+128) ------
    {
        const float4* zb4 = (const float4*)(z + (size_t)b * DIMM * TLEN + t0) + lane;
        u64 acc[8][2];
#pragma unroll
        for (int o = 0; o < 8; o++) { acc[o][0] = 0; acc[o][1] = 0; }
        const int d0 = w * 128;
#pragma unroll 4
        for (int i = 0; i < 128; i++) {
            int d = d0 + i;
            float4 zv = __ldcg(zb4 + (size_t)d * (TLEN / 4));
            u64 zA = pack2(zv.x, zv.y);
            u64 zB = pack2(zv.z, zv.w);
            const ulonglong2* wd = (const ulonglong2*)(g_Wtd + d * 16);
            ulonglong2 w0 = __ldg(wd), w1 = __ldg(wd + 1), w2 = __ldg(wd + 2), w3 = __ldg(wd + 3);
            acc[0][0] = fma2(w0.x, zA, acc[0][0]); acc[0][1] = fma2(w0.x, zB, acc[0][1]);
            acc[1][0] = fma2(w0.y, zA, acc[1][0]); acc[1][1] = fma2(w0.y, zB, acc[1][1]);
            acc[2][0] = fma2(w1.x, zA, acc[2][0]); acc[2][1] = fma2(w1.x, zB, acc[2][1]);
            acc[3][0] = fma2(w1.y, zA, acc[3][0]); acc[3][1] = fma2(w1.y, zB, acc[3][1]);
            acc[4][0] = fma2(w2.x, zA, acc[4][0]); acc[4][1] = fma2(w2.x, zB, acc[4][1]);
            acc[5][0] = fma2(w2.y, zA, acc[5][0]); acc[5][1] = fma2(w2.y, zB, acc[5][1]);
            acc[6][0] = fma2(w3.x, zA, acc[6][0]); acc[6][1] = fma2(w3.x, zB, acc[6][1]);
            acc[7][0] = fma2(w3.y, zA, acc[7][0]); acc[7][1] = fma2(w3.y, zB, acc[7][1]);
        }
        // store partials: s_part[w][lane][o] = float4(t0..t3) for output o
        ulonglong2* sp = (ulonglong2*)(s_raw + ((size_t)(w * 32 + lane) * 9) * 16);
#pragma unroll
        for (int o = 0; o < 8; o++) {
            ulonglong2 v; v.x = acc[o][0]; v.y = acc[o][1];
            sp[o] = v;
        }
    }
    __syncthreads();

    // ---- reduce partials across warps (ascending w, bias last) -------------
    {
        const float* spF = (const float*)s_raw;
#pragma unroll
        for (int j = 0; j < 4; j++) {
            int f = tid + 256 * j;             // 0..1023
            int t = f >> 3, o = f & 7;
            int base = ((t >> 2) * 9 + o) * 4 + (t & 3);   // (lane,o,comp)
            float s = 0.f;
#pragma unroll
            for (int ww = 0; ww < 8; ww++) s += spF[ww * 32 * 9 * 4 + base];
            s += __ldg(b_in + o);
            s_ze[t * 9 + o] = s;
        }
    }
    __syncthreads();

    // ---- normalize queries (threads 0..127, one t each) ---------------------
    if (tid < TILE) {
        int t = tid;
        float ze[8];
#pragma unroll
        for (int k = 0; k < 8; k++) ze[k] = s_ze[t * 9 + k];
        float s = 0.f;
#pragma unroll
        for (int k = 0; k < 8; k++) s = fmaf(ze[k], ze[k], s);
        float den = fmaxf(__fsqrt_rn(s), 1e-12f);
        float q[8];
#pragma unroll
        for (int k = 0; k < 8; k++) q[k] = __fdiv_rn(ze[k], den);
        float esq = 0.f;
#pragma unroll
        for (int k = 0; k < 8; k++) esq = fmaf(q[k], q[k], esq);
#pragma unroll
        for (int k = 0; k < 8; k++) s_q[t * 9 + k] = q[k];
        s_q[t * 9 + 8] = esq;
    }
    __syncthreads();

    // ---- argmin: warp w scans codes [512w,512w+512) for its lanes' 4 t ------
    {
        const int tb = lane * 4;
        u64 qqA[8], qqB[8];
#pragma unroll
        for (int k = 0; k < 8; k++) {
            qqA[k] = pack2(s_q[(tb + 0) * 9 + k], s_q[(tb + 1) * 9 + k]);
            qqB[k] = pack2(s_q[(tb + 2) * 9 + k], s_q[(tb + 3) * 9 + k]);
        }
        const u64 esqA = pack2(s_q[(tb + 0) * 9 + 8], s_q[(tb + 1) * 9 + 8]);
        const u64 esqB = pack2(s_q[(tb + 2) * 9 + 8], s_q[(tb + 3) * 9 + 8]);
        const u64 neg2 = pack2(-2.0f, -2.0f);

        float dmin[4] = {3.402823466e38f, 3.402823466e38f, 3.402823466e38f, 3.402823466e38f};
        int   imin[4] = {0, 0, 0, 0};
        const int j0 = w * 512;
        const ulonglong2* cpb  = (const ulonglong2*)g_cnd + (size_t)j0 * 4;
        const ulonglong2* csqb = (const ulonglong2*)g_csqD + (j0 >> 1);

        for (int it = 0; it < 256; it++) {
            const ulonglong2* cp = cpb + it * 8;
            ulonglong2 c0 = __ldg(cp),     c1 = __ldg(cp + 1), c2 = __ldg(cp + 2), c3 = __ldg(cp + 3);
            ulonglong2 c4 = __ldg(cp + 4), c5 = __ldg(cp + 5), c6 = __ldg(cp + 6), c7 = __ldg(cp + 7);
            ulonglong2 cs = __ldg(csqb + it);
            int j = j0 + it * 2;

            // code j
            u64 dA = 0, dB = 0;
            dA = fma2(c0.x, qqA[0], dA); dB = fma2(c0.x, qqB[0], dB);
            dA = fma2(c0.y, qqA[1], dA); dB = fma2(c0.y, qqB[1], dB);
            dA = fma2(c1.x, qqA[2], dA); dB = fma2(c1.x, qqB[2], dB);
            dA = fma2(c1.y, qqA[3], dA); dB = fma2(c1.y, qqB[3], dB);
            dA = fma2(c2.x, qqA[4], dA); dB = fma2(c2.x, qqB[4], dB);
            dA = fma2(c2.y, qqA[5], dA); dB = fma2(c2.y, qqB[5], dB);
            dA = fma2(c3.x, qqA[6], dA); dB = fma2(c3.x, qqB[6], dB);
            dA = fma2(c3.y, qqA[7], dA); dB = fma2(c3.y, qqB[7], dB);
            u64 distA = add2(fma2(dA, neg2, esqA), cs.x);   // (esq-2dot)+csq, bit-identical
            u64 distB = add2(fma2(dB, neg2, esqB), cs.x);
            {
                float x0, x1, x2, x3;
                unpack2(distA, x0, x1); unpack2(distB, x2, x3);
                if (x0 < dmin[0]) { dmin[0] = x0; imin[0] = j; }
                if (x1 < dmin[1]) { dmin[1] = x1; imin[1] = j; }
                if (x2 < dmin[2]) { dmin[2] = x2; imin[2] = j; }
                if (x3 < dmin[3]) { dmin[3] = x3; imin[3] = j; }
            }
            // code j+1
            u64 eA = 0, eB = 0;
            eA = fma2(c4.x, qqA[0], eA); eB = fma2(c4.x, qqB[0], eB);
            eA = fma2(c4.y, qqA[1], eA); eB = fma2(c4.y, qqB[1], eB);
            eA = fma2(c5.x, qqA[2], eA); eB = fma2(c5.x, qqB[2], eB);
            eA = fma2(c5.y, qqA[3], eA); eB = fma2(c5.y, qqB[3], eB);
            eA = fma2(c6.x, qqA[4], eA); eB = fma2(c6.x, qqB[4], eB);
            eA = fma2(c6.y, qqA[5], eA); eB = fma2(c6.y, qqB[5], eB);
            eA = fma2(c7.x, qqA[6], eA); eB = fma2(c7.x, qqB[6], eB);
            eA = fma2(c7.y, qqA[7], eA); eB = fma2(c7.y, qqB[7], eB);
            u64 dist2A = add2(fma2(eA, neg2, esqA), cs.y);
            u64 dist2B = add2(fma2(eB, neg2, esqB), cs.y);
            {
                float x0, x1, x2, x3;
                unpack2(dist2A, x0, x1); unpack2(dist2B, x2, x3);
                if (x0 < dmin[0]) { dmin[0] = x0; imin[0] = j + 1; }
                if (x1 < dmin[1]) { dmin[1] = x1; imin[1] = j + 1; }
                if (x2 < dmin[2]) { dmin[2] = x2; imin[2] = j + 1; }
                if (x3 < dmin[3]) { dmin[3] = x3; imin[3] = j + 1; }
            }
        }
        *(float4*)(s_dmin + w * 128 + tb) = make_float4(dmin[0], dmin[1], dmin[2], dmin[3]);
        *(int4*)  (s_imin + w * 128 + tb) = make_int4(imin[0], imin[1], imin[2], imin[3]);
    }
    __syncthreads();

    // ---- gather/loss/STE (warps 0..3, one t per lane) -----------------------
    if (w < 4) {
        int t = w * 32 + lane;
        float dm = s_dmin[t];
        int   im = s_imin[t];
#pragma unroll
        for (int ww = 1; ww < 8; ww++) {
            float d = s_dmin[ww * 128 + t];
            if (d < dm) { dm = d; im = s_imin[ww * 128 + t]; }
        }
        const float4* cr = (const float4*)(cb + (size_t)im * 8);
        float4 cA = __ldg(cr), cB = __ldg(cr + 1);
        float zq[8] = {cA.x, cA.y, cA.z, cA.w, cB.x, cB.y, cB.z, cB.w};
        float loss = 0.f;
#pragma unroll
        for (int k = 0; k < 8; k++) {
            float zev = s_ze[t * 9 + k];
            float df = zev - zq[k];
            loss = fmaf(df, df, loss);
            s_zs[t * 9 + k] = zev + (zq[k] - zev);      // straight-through value
        }
#pragma unroll
        for (int off = 16; off >= 1; off >>= 1) loss += __shfl_down_sync(0xffffffffu, loss, off);
        if (lane == 0) s_lw[w] = loss;
        if (write_idx) out[IDX_OFF + tf0 + t] = (float)im;
    }
    __syncthreads();

    if (tid == 0)
        g_partial[blockIdx.x] = ((s_lw[0] + s_lw[1]) + s_lw[2]) + s_lw[3];

    // ---- out_proj: warp w covers o in [128w,128w+128) -----------------------
    {
        const int tb = lane * 4;
        u64 zzA[8], zzB[8];
#pragma unroll
        for (int k = 0; k < 8; k++) {
            zzA[k] = pack2(s_zs[(tb + 0) * 9 + k], s_zs[(tb + 1) * 9 + k]);
            zzB[k] = pack2(s_zs[(tb + 2) * 9 + k], s_zs[(tb + 3) * 9 + k]);
        }
        float* ob = out + (size_t)b * DIMM * TLEN + t0 + tb;
        const int o0 = w * 128;
        const u64* bo = (const u64*)g_boutD;
#pragma unroll 2
        for (int i = 0; i < 128; i++) {
            int o = o0 + i;
            const ulonglong2* wp = (const ulonglong2*)(g_WoutD + o * 16);
            ulonglong2 w0 = __ldg(wp), w1 = __ldg(wp + 1), w2 = __ldg(wp + 2), w3 = __ldg(wp + 3);
            u64 aA = 0, aB = 0;
            aA = fma2(w0.x, zzA[0], aA); aB = fma2(w0.x, zzB[0], aB);
            aA = fma2(w0.y, zzA[1], aA); aB = fma2(w0.y, zzB[1], aB);
            aA = fma2(w1.x, zzA[2], aA); aB = fma2(w1.x, zzB[2], aB);
            aA = fma2(w1.y, zzA[3], aA); aB = fma2(w1.y, zzB[3], aB);
            aA = fma2(w2.x, zzA[4], aA); aB = fma2(w2.x, zzB[4], aB);
            aA = fma2(w2.y, zzA[5], aA); aB = fma2(w2.y, zzB[5], aB);
            aA = fma2(w3.x, zzA[6], aA); aB = fma2(w3.x, zzB[6], aB);
            aA = fma2(w3.y, zzA[7], aA); aB = fma2(w3.y, zzB[7], aB);
            aA = add2(aA, __ldg(bo + o));
            aB = add2(aB, __ldg(bo + o));
            float v0, v1, v2, v3;
            unpack2(aA, v0, v1); unpack2(aB, v2, v3);
            __stcg((float4*)(ob + (size_t)o * TLEN), make_float4(v0, v1, v2, v3));
        }
    }
}

// ---------------- deterministic loss finalization ----------------------------
__global__ void loss_final_kernel(float* __restrict__ out, int write_loss)
{
    if (!write_loss) return;
    int b = threadIdx.x;
    if (b >= BB) return;
    float s = 0.f;
    for (int i = 0; i < NTILES / BB; i++)               // fixed order -> deterministic
        s += g_partial[b * (NTILES / BB) + i];
    out[LOSS_OFF + b] = s * (1.25f / 32768.0f);
}

// ---------------- launch -----------------------------------------------------
extern "C" void kernel_launch(void* const* d_in, const int* in_sizes, int n_in,
                              void* d_out, int out_size)
{
    const float* z     = (const float*)d_in[0];
    const float* v_in  = (const float*)d_in[1];
    const float* g_in  = (const float*)d_in[2];
    const float* b_in  = (const float*)d_in[3];
    const float* cb    = (const float*)d_in[4];
    const float* v_out = (const float*)d_in[5];
    const float* g_out = (const float*)d_in[6];
    const float* b_out = (const float*)d_in[7];
    float* out = (float*)d_out;

    int write_idx  = (out_size >= IDX_OFF + BB * TLEN) ? 1 : 0;
    int write_loss = (out_size >= LOSS_OFF + BB) ? 1 : 0;

    prep_kernel<<<41, 128>>>(v_in, g_in, cb, v_out, g_out, b_out);
    vq_main_kernel<<<NTILES, 256>>>(z, b_in, cb, out, write_idx);
    loss_final_kernel<<<1, 32>>>(out, write_loss);
}

// round 5
// speedup vs baseline: 5.8373x; 1.6762x over previous
#include <cuda_runtime.h>

#define BB   8
#define DIMM 1024
#define TLEN 4096
#define CBN  4096
#define CDN  8
#define TILE 128

#define OUT_ELEMS (BB*DIMM*TLEN)          /* 33554432 */
#define IDX_OFF   OUT_ELEMS
#define LOSS_OFF  (OUT_ELEMS + BB*TLEN)   /* 33587200 */
#define NTILES    ((BB*TLEN)/TILE)        /* 256 */

// ---------------- scratch (device globals; no allocs allowed) ----------------
__device__ __align__(16) float g_Wt[DIMM*CDN];    // W_in^T [d][o]
__device__ __align__(16) float g_Wb[DIMM*12];     // W_out row (8) + bias + pad(3), 48B/row
__device__ __align__(16) float g_cn[CBN*CDN];     // normalized codebook [j][k]
__device__ __align__(16) float g_csq[CBN];        // ||c_n||^2
__device__ float g_partial[NTILES];

// ---------------- prep: weight-norm + normalized codebook --------------------
__global__ void prep_kernel(const float* __restrict__ v_in,  const float* __restrict__ g_in,
                            const float* __restrict__ cb,
                            const float* __restrict__ v_out, const float* __restrict__ g_out,
                            const float* __restrict__ b_out)
{
    int bid = blockIdx.x, tid = threadIdx.x;

    if (bid < 32) {
        int j = bid * 128 + tid;
        const float4* r = (const float4*)(cb + j * 8);
        float4 a = __ldg(r), b = __ldg(r + 1);
        float v[8] = {a.x, a.y, a.z, a.w, b.x, b.y, b.z, b.w};
        float s = 0.f;
#pragma unroll
        for (int k = 0; k < 8; k++) s = fmaf(v[k], v[k], s);
        float den = fmaxf(__fsqrt_rn(s), 1e-12f);
        float c[8];
#pragma unroll
        for (int k = 0; k < 8; k++) c[k] = __fdiv_rn(v[k], den);
        float cs = 0.f;
#pragma unroll
        for (int k = 0; k < 8; k++) cs = fmaf(c[k], c[k], cs);
        g_csq[j] = cs;
        float4* dst = (float4*)(g_cn + j * 8);
        dst[0] = make_float4(c[0], c[1], c[2], c[3]);
        dst[1] = make_float4(c[4], c[5], c[6], c[7]);
    } else if (bid < 40) {
        int o = (bid - 32) * 128 + tid;
        const float4* r = (const float4*)(v_out + o * 8);
        float4 a = __ldg(r), b = __ldg(r + 1);
        float v[8] = {a.x, a.y, a.z, a.w, b.x, b.y, b.z, b.w};
        float s = 0.f;
#pragma unroll
        for (int k = 0; k < 8; k++) s = fmaf(v[k], v[k], s);
        float n = __fsqrt_rn(s);
        float g = __ldg(g_out + o);
        float w[8];
#pragma unroll
        for (int k = 0; k < 8; k++) w[k] = __fdiv_rn(g * v[k], n);
        float4* dst = (float4*)(g_Wb + o * 12);
        dst[0] = make_float4(w[0], w[1], w[2], w[3]);
        dst[1] = make_float4(w[4], w[5], w[6], w[7]);
        dst[2] = make_float4(__ldg(b_out + o), 0.f, 0.f, 0.f);
    } else {
        // W_in: 8 rows, norms over 1024 (identical reduction pattern/bits as before)
        __shared__ float nrm[8];
        int o = tid >> 4, l = tid & 15;
        float s = 0.f;
        for (int d = l; d < DIMM; d += 16) {
            float v = v_in[o * DIMM + d];
            s = fmaf(v, v, s);
        }
#pragma unroll
        for (int off = 8; off >= 1; off >>= 1) s += __shfl_down_sync(0xffffffffu, s, off, 16);
        if (l == 0) nrm[o] = __fsqrt_rn(s);
        __syncthreads();
        for (int e = tid; e < DIMM * CDN; e += 128) {
            int d = e >> 3, oo = e & 7;
            g_Wt[e] = __fdiv_rn(__ldg(g_in + oo) * v_in[oo * DIMM + d], nrm[oo]);
        }
    }
}

// ---------------- fused main: TILE=128 t/block, 4 t per lane, scalar FFMA ----
// smem: [0,36864) partials float4[8w][32lane][9]; reused after reduce:
//       [0,4608) s_q [128t][9]; [4608,9216) s_zs [128t][9];
//       [9216,13312) s_dmin [8w][128t]; [13312,17408) s_imin;
//       [36864,41472) s_ze [128t][9] persistent; [41472,41488) s_lw[4]
__global__ void __launch_bounds__(256, 2)
vq_main_kernel(const float* __restrict__ z, const float* __restrict__ b_in,
               const float* __restrict__ cb, float* __restrict__ out, int write_idx)
{
    __shared__ __align__(16) unsigned char s_raw[41504];
    float* s_ze   = (float*)(s_raw + 36864);
    float* s_lw   = (float*)(s_raw + 41472);
    float* s_q    = (float*)(s_raw);
    float* s_zs   = (float*)(s_raw + 4608);
    float* s_dmin = (float*)(s_raw + 9216);
    int*   s_imin = (int*)  (s_raw + 13312);

    const int tid  = threadIdx.x;
    const int w    = tid >> 5;
    const int lane = tid & 31;
    const int tf0  = blockIdx.x * TILE;    // 128 consecutive t, same b
    const int b    = tf0 >> 12;
    const int t0   = tf0 & (TLEN - 1);

    // ---- phase 1: in_proj partials. warp w covers d in [128w,128w+128) ------
    {
        const float4* zb4 = (const float4*)(z + (size_t)b * DIMM * TLEN + t0) + lane;
        float acc[8][4];
#pragma unroll
        for (int o = 0; o < 8; o++)
#pragma unroll
            for (int t = 0; t < 4; t++) acc[o][t] = 0.f;
        const int d0 = w * 128;
#pragma unroll 4
        for (int i = 0; i < 128; i++) {
            int d = d0 + i;
            float4 zv = __ldcg(zb4 + (size_t)d * (TLEN / 4));
            const float4* wr = (const float4*)(g_Wt + d * 8);
            float4 wA = __ldg(wr), wB = __ldg(wr + 1);
            float wv[8] = {wA.x, wA.y, wA.z, wA.w, wB.x, wB.y, wB.z, wB.w};
#pragma unroll
            for (int o = 0; o < 8; o++) {
                acc[o][0] = fmaf(wv[o], zv.x, acc[o][0]);
                acc[o][1] = fmaf(wv[o], zv.y, acc[o][1]);
                acc[o][2] = fmaf(wv[o], zv.z, acc[o][2]);
                acc[o][3] = fmaf(wv[o], zv.w, acc[o][3]);
            }
        }
        float4* sp = (float4*)(s_raw + ((size_t)(w * 32 + lane) * 9) * 16);
#pragma unroll
        for (int o = 0; o < 8; o++)
            sp[o] = make_float4(acc[o][0], acc[o][1], acc[o][2], acc[o][3]);
    }
    __syncthreads();

    // ---- reduce partials across warps (ascending w, bias last) --------------
    {
        const float* spF = (const float*)s_raw;
#pragma unroll
        for (int j = 0; j < 4; j++) {
            int f = tid + 256 * j;             // 0..1023
            int t = f >> 3, o = f & 7;
            int base = ((t >> 2) * 9 + o) * 4 + (t & 3);
            float s = 0.f;
#pragma unroll
            for (int ww = 0; ww < 8; ww++) s += spF[ww * 32 * 9 * 4 + base];
            s += __ldg(b_in + o);
            s_ze[t * 9 + o] = s;
        }
    }
    __syncthreads();

    // ---- normalize queries (threads 0..127) ---------------------------------
    if (tid < TILE) {
        int t = tid;
        float ze[8];
#pragma unroll
        for (int k = 0; k < 8; k++) ze[k] = s_ze[t * 9 + k];
        float s = 0.f;
#pragma unroll
        for (int k = 0; k < 8; k++) s = fmaf(ze[k], ze[k], s);
        float den = fmaxf(__fsqrt_rn(s), 1e-12f);
        float q[8];
#pragma unroll
        for (int k = 0; k < 8; k++) q[k] = __fdiv_rn(ze[k], den);
        float esq = 0.f;
#pragma unroll
        for (int k = 0; k < 8; k++) esq = fmaf(q[k], q[k], esq);
#pragma unroll
        for (int k = 0; k < 8; k++) s_q[t * 9 + k] = q[k];
        s_q[t * 9 + 8] = esq;
    }
    __syncthreads();

    // ---- argmin: warp w scans codes [512w,512w+512); lane owns 4 t ----------
    {
        const int tb = lane * 4;
        float q[4][8], esq[4];
#pragma unroll
        for (int t = 0; t < 4; t++) {
#pragma unroll
            for (int k = 0; k < 8; k++) q[t][k] = s_q[(tb + t) * 9 + k];
            esq[t] = s_q[(tb + t) * 9 + 8];
        }

        float dmin[4] = {3.402823466e38f, 3.402823466e38f, 3.402823466e38f, 3.402823466e38f};
        int   imin[4] = {0, 0, 0, 0};
        const int j0 = w * 512;
        const float4* crow = (const float4*)g_cn + (size_t)j0 * 2;
        const float2* cq   = (const float2*)g_csq + (j0 >> 1);

        for (int it = 0; it < 256; it++) {
            const float4* cp = crow + it * 4;
            float4 a0 = __ldg(cp),     a1 = __ldg(cp + 1);
            float4 b0 = __ldg(cp + 2), b1 = __ldg(cp + 3);
            float2 cs = __ldg(cq + it);
            const int j = j0 + it * 2;
            float cA[8] = {a0.x, a0.y, a0.z, a0.w, a1.x, a1.y, a1.z, a1.w};
            float cB[8] = {b0.x, b0.y, b0.z, b0.w, b1.x, b1.y, b1.z, b1.w};

            float dotA[4], dotB[4];
#pragma unroll
            for (int t = 0; t < 4; t++) {
                float sA = 0.f, sB = 0.f;
#pragma unroll
                for (int k = 0; k < 8; k++) {
                    sA = fmaf(cA[k], q[t][k], sA);
                    sB = fmaf(cB[k], q[t][k], sB);
                }
                dotA[t] = sA; dotB[t] = sB;
            }
#pragma unroll
            for (int t = 0; t < 4; t++) {
                float dist = fmaf(dotA[t], -2.0f, esq[t]) + cs.x;   // bit-identical order
                if (dist < dmin[t]) { dmin[t] = dist; imin[t] = j; }
            }
#pragma unroll
            for (int t = 0; t < 4; t++) {
                float dist = fmaf(dotB[t], -2.0f, esq[t]) + cs.y;
                if (dist < dmin[t]) { dmin[t] = dist; imin[t] = j + 1; }
            }
        }
        *(float4*)(s_dmin + w * 128 + tb) = make_float4(dmin[0], dmin[1], dmin[2], dmin[3]);
        *(int4*)  (s_imin + w * 128 + tb) = make_int4(imin[0], imin[1], imin[2], imin[3]);
    }
    __syncthreads();

    // ---- gather/loss/STE (warps 0..3, one t per lane) -----------------------
    if (w < 4) {
        int t = w * 32 + lane;
        float dm = s_dmin[t];
        int   im = s_imin[t];
#pragma unroll
        for (int ww = 1; ww < 8; ww++) {
            float d = s_dmin[ww * 128 + t];
            if (d < dm) { dm = d; im = s_imin[ww * 128 + t]; }
        }
        const float4* cr = (const float4*)(cb + (size_t)im * 8);
        float4 cA = __ldg(cr), cB = __ldg(cr + 1);
        float zq[8] = {cA.x, cA.y, cA.z, cA.w, cB.x, cB.y, cB.z, cB.w};
        float loss = 0.f;
#pragma unroll
        for (int k = 0; k < 8; k++) {
            float zev = s_ze[t * 9 + k];
            float df = zev - zq[k];
            loss = fmaf(df, df, loss);
            s_zs[t * 9 + k] = zev + (zq[k] - zev);
        }
#pragma unroll
        for (int off = 16; off >= 1; off >>= 1) loss += __shfl_down_sync(0xffffffffu, loss, off);
        if (lane == 0) s_lw[w] = loss;
        if (write_idx) out[IDX_OFF + tf0 + t] = (float)im;
    }
    __syncthreads();

    if (tid == 0)
        g_partial[blockIdx.x] = ((s_lw[0] + s_lw[1]) + s_lw[2]) + s_lw[3];

    // ---- out_proj: warp w covers o in [128w,128w+128); lane owns 4 t --------
    {
        const int tb = lane * 4;
        float zs[4][8];
#pragma unroll
        for (int t = 0; t < 4; t++)
#pragma unroll
            for (int k = 0; k < 8; k++) zs[t][k] = s_zs[(tb + t) * 9 + k];

        float* ob = out + (size_t)b * DIMM * TLEN + t0 + tb;
        const int o0 = w * 128;
#pragma unroll 4
        for (int i = 0; i < 128; i++) {
            int o = o0 + i;
            const float4* wr = (const float4*)(g_Wb + o * 12);
            float4 wA = __ldg(wr), wB = __ldg(wr + 1), wC = __ldg(wr + 2);
            float wv[8] = {wA.x, wA.y, wA.z, wA.w, wB.x, wB.y, wB.z, wB.w};
            float r[4];
#pragma unroll
            for (int t = 0; t < 4; t++) {
                float s = 0.f;
#pragma unroll
                for (int k = 0; k < 8; k++) s = fmaf(wv[k], zs[t][k], s);
                r[t] = s + wC.x;                       // bias last, same bits
            }
            __stcg((float4*)(ob + (size_t)o * TLEN), make_float4(r[0], r[1], r[2], r[3]));
        }
    }
}

// ---------------- deterministic loss finalization ----------------------------
__global__ void loss_final_kernel(float* __restrict__ out, int write_loss)
{
    if (!write_loss) return;
    int b = threadIdx.x;
    if (b >= BB) return;
    float s = 0.f;
    for (int i = 0; i < NTILES / BB; i++)
        s += g_partial[b * (NTILES / BB) + i];
    out[LOSS_OFF + b] = s * (1.25f / 32768.0f);
}

// ---------------- launch -----------------------------------------------------
extern "C" void kernel_launch(void* const* d_in, const int* in_sizes, int n_in,
                              void* d_out, int out_size)
{
    const float* z     = (const float*)d_in[0];
    const float* v_in  = (const float*)d_in[1];
    const float* g_in  = (const float*)d_in[2];
    const float* b_in  = (const float*)d_in[3];
    const float* cb    = (const float*)d_in[4];
    const float* v_out = (const float*)d_in[5];
    const float* g_out = (const float*)d_in[6];
    const float* b_out = (const float*)d_in[7];
    float* out = (float*)d_out;

    int write_idx  = (out_size >= IDX_OFF + BB * TLEN) ? 1 : 0;
    int write_loss = (out_size >= LOSS_OFF + BB) ? 1 : 0;

    prep_kernel<<<41, 128>>>(v_in, g_in, cb, v_out, g_out, b_out);
    vq_main_kernel<<<NTILES, 256>>>(z, b_in, cb, out, write_idx);
    loss_final_kernel<<<1, 32>>>(out, write_loss);
}